// round 16
// baseline (speedup 1.0000x reference)
#include <cuda_runtime.h>
#include <cuda_fp16.h>
#include <math.h>
#include <stdint.h>

constexpr int S_ = 2048;
constexpr float QSCALE = 0.18033688011112042592f;  // 0.125 * log2(e)

// ---------------------------------------------------------------------------
// Scratch, allocation-free device globals (fp16 hi, 1-term everywhere).
// ---------------------------------------------------------------------------
__device__ __half g_xh[8388608];
__device__ __half g_wh[3145728];
__device__ __half g_woh[1048576];
__device__ __half g_qh[8388608];
__device__ __half g_kh[8388608];
__device__ __half g_vh[8388608];
__device__ __half g_atth[8388608];

// ---------------------------------------------------------------------------
// Helpers
// ---------------------------------------------------------------------------
__device__ __forceinline__ uint32_t smem_u32(const void* p) {
    uint32_t a;
    asm("{ .reg .u64 t; cvta.to.shared.u64 t, %1; cvt.u32.u64 %0, t; }" : "=r"(a) : "l"(p));
    return a;
}
__device__ __forceinline__ uint32_t pack_h2(float a, float b) {
    __half2 h = __floats2half2_rn(a, b);
    return *reinterpret_cast<uint32_t*>(&h);
}
__device__ __forceinline__ float fast_exp2(float x) {
    float y;
    asm("ex2.approx.ftz.f32 %0, %1;" : "=f"(y) : "f"(x));
    return y;
}
__device__ __forceinline__ void mma_f16(float c[4], const uint32_t a[4],
                                        uint32_t b0, uint32_t b1) {
    asm("mma.sync.aligned.m16n8k16.row.col.f32.f16.f16.f32 "
        "{%0,%1,%2,%3}, {%4,%5,%6,%7}, {%8,%9}, {%0,%1,%2,%3};"
        : "+f"(c[0]), "+f"(c[1]), "+f"(c[2]), "+f"(c[3])
        : "r"(a[0]), "r"(a[1]), "r"(a[2]), "r"(a[3]), "r"(b0), "r"(b1));
}
__device__ __forceinline__ void cp16(uint32_t s, const void* g) {
    asm volatile("{ .reg .u64 gp; cvta.to.global.u64 gp, %1;"
                 " cp.async.cg.shared.global [%0], [gp], 16; }"
                 :: "r"(s), "l"(g) : "memory");
}
#define CP_COMMIT() asm volatile("cp.async.commit_group;" ::: "memory")
#define CP_WAIT(n)  asm volatile("cp.async.wait_group %0;" :: "n"(n) : "memory")
#define LDSM_X4(R, addr) \
    asm volatile("ldmatrix.sync.aligned.m8n8.x4.shared.b16 {%0,%1,%2,%3}, [%4];" \
        : "=r"((R)[0]), "=r"((R)[1]), "=r"((R)[2]), "=r"((R)[3]) : "r"(addr))
#define LDSM_X4T(R, addr) \
    asm volatile("ldmatrix.sync.aligned.m8n8.x4.trans.shared.b16 {%0,%1,%2,%3}, [%4];" \
        : "=r"((R)[0]), "=r"((R)[1]), "=r"((R)[2]), "=r"((R)[3]) : "r"(addr))

// ---------------------------------------------------------------------------
// Fused fp32 -> fp16 conversion: blocks [0, 8192) convert x (2M float4),
// blocks [8192, 9216) convert Wo (256K float4).
// ---------------------------------------------------------------------------
__global__ __launch_bounds__(256) void conv_fused_kernel(
    const float4* __restrict__ x, uint32_t* __restrict__ xh,
    const float4* __restrict__ wo, uint32_t* __restrict__ woh)
{
    const float4* src;
    uint32_t* dst;
    int i;
    if (blockIdx.x < 8192) {
        src = x;  dst = xh;
        i = blockIdx.x * 256 + threadIdx.x;
    } else {
        src = wo; dst = woh;
        i = (blockIdx.x - 8192) * 256 + threadIdx.x;
    }
    float4 v = src[i];
    dst[2 * i]     = pack_h2(v.x, v.y);
    dst[2 * i + 1] = pack_h2(v.z, v.w);
}

// ---------------------------------------------------------------------------
// qkv weight transpose (fp16 hi only)
// ---------------------------------------------------------------------------
__global__ __launch_bounds__(256) void wtrans_kernel(
    const float* __restrict__ Wq, const float* __restrict__ Wk,
    const float* __restrict__ Wv)
{
    __shared__ float tile[64][65];
    const int selh = blockIdx.x;
    const int sel  = selh >> 4;
    const int h    = selh & 15;
    const int d0   = blockIdx.y * 64;
    const float* W  = (sel == 0) ? Wq : (sel == 1) ? Wk : Wv;
    const float* Wb = W + (size_t)h * 1024 * 64;

    const int tid = threadIdx.x;
    for (int idx = tid; idx < 64 * 64; idx += 256) {
        int r = idx >> 6, c = idx & 63;
        tile[r][c] = Wb[(size_t)(d0 + r) * 64 + c];
    }
    __syncthreads();
    const size_t nbase = (size_t)sel * 1024 + h * 64;
    for (int idx = tid; idx < 2048; idx += 256) {
        int r  = idx >> 5;
        int c2 = (idx & 31) * 2;
        size_t o = (nbase + r) * 1024 + d0 + c2;
        *(uint32_t*)&g_wh[o] = pack_h2(tile[c2][r], tile[c2 + 1][r]);
    }
}

// ---------------------------------------------------------------------------
// Pure fp16 GEMM: C = Ah @ Bh^T. Warp tile 64x64, block 128x128.
// K-chunk 64 (one sync per 64 K), cp.async double-buffered.
// smem stage = A 18432 + B 18432 = 36864 B; 2 stages = 73728 -> 2 CTAs/SM.
// mode 0: write q (scaled)/k/v fp16. mode 1: fp32 out.
// ---------------------------------------------------------------------------
__global__ __launch_bounds__(128, 2) void gemm_kernel(
    const __half* __restrict__ Ah, const __half* __restrict__ Bh,
    float* __restrict__ out, int mode)
{
    extern __shared__ __half dsm[];
    constexpr uint32_t ARR = 18432, STG = 36864;   // 2 stages -> 73728 B

    const int m0 = blockIdx.y * 128;
    const int n0 = blockIdx.x * 128;
    const int tid = threadIdx.x;
    const int w = tid >> 5, lane = tid & 31;
    const int wm = w >> 1, wn = w & 1;
    const int gr = lane >> 2, tg = lane & 3;
    const uint32_t sbase = smem_u32(dsm);

    float C[4][8][4];
    #pragma unroll
    for (int a = 0; a < 4; a++)
        #pragma unroll
        for (int b = 0; b < 8; b++)
            #pragma unroll
            for (int c = 0; c < 4; c++) C[a][b][c] = 0.0f;

    const uint32_t a_rowb = (uint32_t)(wm * 64 + (lane & 7) + ((lane & 8) ? 8 : 0));
    const uint32_t a_coff = (lane & 16) ? 8 : 0;
    const uint32_t b_rowb = (uint32_t)(wn * 64 + (lane & 7) + ((lane & 16) ? 8 : 0));
    const uint32_t b_coff = (lane & 8) ? 8 : 0;

    auto stage_load = [&](int it, int buf) {
        const int k0 = it * 64;
        const uint32_t sa = sbase + (uint32_t)buf * STG;
        // 128 rows x 64 cols fp16 per array: 8 x 16B chunks per row
        #pragma unroll
        for (int i = 0; i < 8; i++) {
            const int idx = tid + 128 * i;
            const int row = idx >> 3;
            const int c8  = idx & 7;
            const uint32_t so = (uint32_t)(row * 144 + c8 * 16);
            cp16(sa + so,       Ah + (size_t)(m0 + row) * 1024 + k0 + c8 * 8);
            cp16(sa + ARR + so, Bh + (size_t)(n0 + row) * 1024 + k0 + c8 * 8);
        }
        CP_COMMIT();
    };

    stage_load(0, 0);
    for (int it = 0; it < 16; it++) {
        const int buf = it & 1;
        CP_WAIT(0);
        __syncthreads();
        if (it + 1 < 16) stage_load(it + 1, 1 - buf);
        const uint32_t sa = sbase + (uint32_t)buf * STG;

        #pragma unroll
        for (int ks = 0; ks < 4; ks++) {
            const uint32_t acol = (uint32_t)(ks * 16) + a_coff;
            const uint32_t bcol = (uint32_t)(ks * 16) + b_coff;
            uint32_t ah[4][4];
            #pragma unroll
            for (int mf = 0; mf < 4; mf++)
                LDSM_X4(ah[mf], sa + (a_rowb + mf * 16) * 144 + acol * 2);
            #pragma unroll
            for (int np = 0; np < 4; np++) {
                uint32_t rh[4];
                LDSM_X4(rh, sa + ARR + (b_rowb + np * 16) * 144 + bcol * 2);
                const int nf0 = np * 2, nf1 = np * 2 + 1;
                #pragma unroll
                for (int mf = 0; mf < 4; mf++) {
                    mma_f16(C[mf][nf0], ah[mf], rh[0], rh[1]);
                    mma_f16(C[mf][nf1], ah[mf], rh[2], rh[3]);
                }
            }
        }
    }

    if (mode == 1) {
        #pragma unroll
        for (int mf = 0; mf < 4; mf++) {
            int row = m0 + wm * 64 + mf * 16 + gr;
            #pragma unroll
            for (int nf = 0; nf < 8; nf++) {
                int col = n0 + wn * 64 + nf * 8 + tg * 2;
                *(float2*)(out + (size_t)row * 1024 + col) =
                    make_float2(C[mf][nf][0], C[mf][nf][1]);
                *(float2*)(out + (size_t)(row + 8) * 1024 + col) =
                    make_float2(C[mf][nf][2], C[mf][nf][3]);
            }
        }
    } else {
        #pragma unroll
        for (int mf = 0; mf < 4; mf++) {
            int row = m0 + wm * 64 + mf * 16 + gr;
            int b = row >> 11, s = row & 2047;
            #pragma unroll
            for (int nf = 0; nf < 8; nf++) {
                int col = n0 + wn * 64 + nf * 8 + tg * 2;
                int sel = col >> 10;
                int hh  = (col >> 6) & 15;
                int kk  = col & 63;
                __half* dst = (sel == 0) ? g_qh : (sel == 1) ? g_kh : g_vh;
                float sc = (sel == 0) ? QSCALE : 1.0f;
                size_t i0 = ((size_t)(b * 16 + hh) * 2048 + s) * 64 + kk;
                size_t i1 = i0 + 8 * 64;
                *(uint32_t*)&dst[i0] = pack_h2(C[mf][nf][0] * sc, C[mf][nf][1] * sc);
                *(uint32_t*)&dst[i1] = pack_h2(C[mf][nf][2] * sc, C[mf][nf][3] * sc);
            }
        }
    }
}

// ---------------------------------------------------------------------------
// Flash attention (causal), pure fp16: S = Qh@Kh^T, O = Ph@Vh (1 pass each).
// 256 thr, q-tile 128, kv-tiles 64, cp.async double-buffered KV, Q persistent.
// smem: KV 2 x 18432 + Q 18432 = 55296 B -> 2 CTAs/SM.
// ---------------------------------------------------------------------------
__global__ __launch_bounds__(256, 2) void attn_kernel()
{
    extern __shared__ __half dsmh[];
    constexpr uint32_t KARR = 9216;           // 64 rows * 144 B
    constexpr uint32_t KSTG = 18432;          // K + V per stage
    constexpr uint32_t QOFF = 36864;

    const int qb = (int)gridDim.x - 1 - (int)blockIdx.x;  // heavy blocks first
    const int q0 = qb * 128;
    const int bh = blockIdx.y;
    const int tid = threadIdx.x;
    const int w = tid >> 5, lane = tid & 31;
    const int gr = lane >> 2, tg = lane & 3;
    const size_t seqbase = (size_t)bh * 2048;
    const uint32_t sbase = smem_u32(dsmh);

    {
        const __half* qh = g_qh + (seqbase + q0) * 64;
        #pragma unroll
        for (int i = 0; i < 4; i++) {
            int c = tid + 256 * i;
            int row = c >> 3, c8 = c & 7;
            uint32_t so = (uint32_t)(row * 144 + c8 * 16);
            cp16(sbase + QOFF + so, qh + (size_t)row * 64 + c8 * 8);
        }
        CP_COMMIT();
    }

    auto stage_kv = [&](int it, int buf) {
        const int kv0 = it * 64;
        const uint32_t sa = sbase + (uint32_t)buf * KSTG;
        const __half* kh = g_kh + (seqbase + kv0) * 64;
        const __half* vh = g_vh + (seqbase + kv0) * 64;
        #pragma unroll
        for (int i = 0; i < 2; i++) {
            int c = tid + 256 * i;
            int row = c >> 3, c8 = c & 7;
            uint32_t so = (uint32_t)(row * 144 + c8 * 16);
            size_t go = (size_t)row * 64 + c8 * 8;
            cp16(sa + so,        kh + go);
            cp16(sa + KARR + so, vh + go);
        }
        CP_COMMIT();
    };

    const int nt = qb * 2 + 2;
    stage_kv(0, 0);
    CP_WAIT(1);
    __syncthreads();

    uint32_t Qh[4][4];
    {
        const uint32_t q_rowb = (uint32_t)(w * 16 + (lane & 7) + ((lane & 8) ? 8 : 0));
        const uint32_t q_coff = (lane & 16) ? 8 : 0;
        #pragma unroll
        for (int ks = 0; ks < 4; ks++)
            LDSM_X4(Qh[ks], sbase + QOFF + q_rowb * 144 + (ks * 16 + q_coff) * 2);
    }

    float O[8][4];
    #pragma unroll
    for (int nf = 0; nf < 8; nf++)
        #pragma unroll
        for (int c = 0; c < 4; c++) O[nf][c] = 0.0f;
    float m0v = -1e30f, m1v = -1e30f, l0v = 0.0f, l1v = 0.0f;
    const int wrow = q0 + w * 16;

    const uint32_t k_rowb = (uint32_t)((lane & 7) + ((lane & 16) ? 8 : 0));
    const uint32_t k_coff = (lane & 8) ? 8 : 0;
    const uint32_t v_coff = (lane & 16) ? 8 : 0;

    for (int it = 0; it < nt; it++) {
        const int buf = it & 1;
        CP_WAIT(0);
        __syncthreads();
        if (it + 1 < nt) stage_kv(it + 1, 1 - buf);
        const int kv0 = it * 64;

        if (kv0 <= wrow + 15) {
            const uint32_t sa = sbase + (uint32_t)buf * KSTG;

            float Sf[8][4];
            #pragma unroll
            for (int nf = 0; nf < 8; nf++)
                #pragma unroll
                for (int c = 0; c < 4; c++) Sf[nf][c] = 0.0f;

            #pragma unroll
            for (int ks = 0; ks < 4; ks++) {
                const uint32_t kcol = (uint32_t)(ks * 16) + k_coff;
                uint32_t rk[4][4];
                #pragma unroll
                for (int np = 0; np < 4; np++)
                    LDSM_X4(rk[np], sa + (k_rowb + np * 16) * 144 + kcol * 2);
                #pragma unroll
                for (int np = 0; np < 4; np++) {
                    mma_f16(Sf[np * 2],     Qh[ks], rk[np][0], rk[np][1]);
                    mma_f16(Sf[np * 2 + 1], Qh[ks], rk[np][2], rk[np][3]);
                }
            }

            if (kv0 + 63 > wrow) {
                const int r0g = wrow + gr;
                #pragma unroll
                for (int nf = 0; nf < 8; nf++) {
                    int col = kv0 + nf * 8 + tg * 2;
                    if (col     > r0g)     Sf[nf][0] = -1e30f;
                    if (col + 1 > r0g)     Sf[nf][1] = -1e30f;
                    if (col     > r0g + 8) Sf[nf][2] = -1e30f;
                    if (col + 1 > r0g + 8) Sf[nf][3] = -1e30f;
                }
            }

            float mx0 = -1e30f, mx1 = -1e30f;
            #pragma unroll
            for (int nf = 0; nf < 8; nf++) {
                mx0 = fmaxf(mx0, fmaxf(Sf[nf][0], Sf[nf][1]));
                mx1 = fmaxf(mx1, fmaxf(Sf[nf][2], Sf[nf][3]));
            }
            mx0 = fmaxf(mx0, __shfl_xor_sync(0xffffffffu, mx0, 1));
            mx0 = fmaxf(mx0, __shfl_xor_sync(0xffffffffu, mx0, 2));
            mx1 = fmaxf(mx1, __shfl_xor_sync(0xffffffffu, mx1, 1));
            mx1 = fmaxf(mx1, __shfl_xor_sync(0xffffffffu, mx1, 2));

            float mn0 = fmaxf(m0v, mx0), mn1 = fmaxf(m1v, mx1);
            float a0 = fast_exp2(m0v - mn0), a1 = fast_exp2(m1v - mn1);
            float s0 = 0.0f, s1 = 0.0f;
            #pragma unroll
            for (int nf = 0; nf < 8; nf++) {
                Sf[nf][0] = fast_exp2(Sf[nf][0] - mn0); s0 += Sf[nf][0];
                Sf[nf][1] = fast_exp2(Sf[nf][1] - mn0); s0 += Sf[nf][1];
                Sf[nf][2] = fast_exp2(Sf[nf][2] - mn1); s1 += Sf[nf][2];
                Sf[nf][3] = fast_exp2(Sf[nf][3] - mn1); s1 += Sf[nf][3];
            }
            s0 += __shfl_xor_sync(0xffffffffu, s0, 1);
            s0 += __shfl_xor_sync(0xffffffffu, s0, 2);
            s1 += __shfl_xor_sync(0xffffffffu, s1, 1);
            s1 += __shfl_xor_sync(0xffffffffu, s1, 2);

            l0v = l0v * a0 + s0;  l1v = l1v * a1 + s1;
            m0v = mn0;            m1v = mn1;
            #pragma unroll
            for (int nf = 0; nf < 8; nf++) {
                O[nf][0] *= a0; O[nf][1] *= a0;
                O[nf][2] *= a1; O[nf][3] *= a1;
            }

            #pragma unroll
            for (int ks = 0; ks < 4; ks++) {
                uint32_t Ph[4];
                Ph[0] = pack_h2(Sf[2 * ks][0],     Sf[2 * ks][1]);
                Ph[1] = pack_h2(Sf[2 * ks][2],     Sf[2 * ks][3]);
                Ph[2] = pack_h2(Sf[2 * ks + 1][0], Sf[2 * ks + 1][1]);
                Ph[3] = pack_h2(Sf[2 * ks + 1][2], Sf[2 * ks + 1][3]);
                const uint32_t v_rowb = (uint32_t)(ks * 16 + (lane & 15));
                uint32_t rv[4][4];
                #pragma unroll
                for (int np = 0; np < 4; np++)
                    LDSM_X4T(rv[np], sa + KARR + v_rowb * 144
                                   + ((uint32_t)(np * 16) + v_coff) * 2);
                #pragma unroll
                for (int np = 0; np < 4; np++) {
                    mma_f16(O[np * 2],     Ph, rv[np][0], rv[np][1]);
                    mma_f16(O[np * 2 + 1], Ph, rv[np][2], rv[np][3]);
                }
            }
        }
    }

    const float inv0 = 1.0f / l0v, inv1 = 1.0f / l1v;
    const int b = bh >> 4, h = bh & 15;
    const int row0 = q0 + w * 16 + gr;
    const size_t base0 = ((size_t)(b * 2048) + row0) * 1024 + h * 64;
    const size_t base1 = base0 + (size_t)8 * 1024;
    #pragma unroll
    for (int nf = 0; nf < 8; nf++) {
        int c = nf * 8 + tg * 2;
        *(uint32_t*)&g_atth[base0 + c] = pack_h2(O[nf][0] * inv0, O[nf][1] * inv0);
        *(uint32_t*)&g_atth[base1 + c] = pack_h2(O[nf][2] * inv1, O[nf][3] * inv1);
    }
}

// ---------------------------------------------------------------------------
extern "C" void kernel_launch(void* const* d_in, const int* in_sizes, int n_in,
                              void* d_out, int out_size)
{
    const float* x  = (const float*)d_in[0];
    const float* Wq = (const float*)d_in[1];
    const float* Wk = (const float*)d_in[2];
    const float* Wv = (const float*)d_in[3];
    const float* Wo = (const float*)d_in[4];
    float* out = (float*)d_out;

    void *p_xh, *p_wh, *p_woh, *p_atth;
    cudaGetSymbolAddress(&p_xh,  g_xh);
    cudaGetSymbolAddress(&p_wh,  g_wh);
    cudaGetSymbolAddress(&p_woh, g_woh);
    cudaGetSymbolAddress(&p_atth, g_atth);

    const int gemm_shm = 73728;   // 2 stages x 36864 (K-chunk 64)
    const int attn_shm = 55296;   // KV 2x18432 + Q 18432
    cudaFuncSetAttribute(gemm_kernel, cudaFuncAttributeMaxDynamicSharedMemorySize, gemm_shm);
    cudaFuncSetAttribute(attn_kernel, cudaFuncAttributeMaxDynamicSharedMemorySize, attn_shm);

    conv_fused_kernel<<<9216, 256>>>((const float4*)x, (uint32_t*)p_xh,
                                     (const float4*)Wo, (uint32_t*)p_woh);

    wtrans_kernel<<<dim3(48, 16), 256>>>(Wq, Wk, Wv);

    gemm_kernel<<<dim3(24, 64), 128, gemm_shm>>>(
        (const __half*)p_xh, (const __half*)p_wh, nullptr, 0);

    attn_kernel<<<dim3(S_ / 128, 64), 256, attn_shm>>>();

    gemm_kernel<<<dim3(8, 64), 128, gemm_shm>>>(
        (const __half*)p_atth, (const __half*)p_woh, out, 1);
}

// round 17
// speedup vs baseline: 1.0432x; 1.0432x over previous
#include <cuda_runtime.h>
#include <cuda_fp16.h>
#include <math.h>
#include <stdint.h>

constexpr int S_ = 2048;
constexpr float QSCALE = 0.18033688011112042592f;  // 0.125 * log2(e)

// ---------------------------------------------------------------------------
// Scratch, allocation-free device globals (fp16 hi, 1-term everywhere).
// ---------------------------------------------------------------------------
__device__ __half g_xh[8388608];
__device__ __half g_wh[3145728];
__device__ __half g_woh[1048576];
__device__ __half g_qh[8388608];
__device__ __half g_kh[8388608];
__device__ __half g_vh[8388608];
__device__ __half g_atth[8388608];

// ---------------------------------------------------------------------------
// Helpers
// ---------------------------------------------------------------------------
__device__ __forceinline__ uint32_t smem_u32(const void* p) {
    uint32_t a;
    asm("{ .reg .u64 t; cvta.to.shared.u64 t, %1; cvt.u32.u64 %0, t; }" : "=r"(a) : "l"(p));
    return a;
}
__device__ __forceinline__ uint32_t pack_h2(float a, float b) {
    __half2 h = __floats2half2_rn(a, b);
    return *reinterpret_cast<uint32_t*>(&h);
}
__device__ __forceinline__ float fast_exp2(float x) {
    float y;
    asm("ex2.approx.ftz.f32 %0, %1;" : "=f"(y) : "f"(x));
    return y;
}
__device__ __forceinline__ void mma_f16(float c[4], const uint32_t a[4],
                                        uint32_t b0, uint32_t b1) {
    asm("mma.sync.aligned.m16n8k16.row.col.f32.f16.f16.f32 "
        "{%0,%1,%2,%3}, {%4,%5,%6,%7}, {%8,%9}, {%0,%1,%2,%3};"
        : "+f"(c[0]), "+f"(c[1]), "+f"(c[2]), "+f"(c[3])
        : "r"(a[0]), "r"(a[1]), "r"(a[2]), "r"(a[3]), "r"(b0), "r"(b1));
}
__device__ __forceinline__ void cp16(uint32_t s, const void* g) {
    asm volatile("{ .reg .u64 gp; cvta.to.global.u64 gp, %1;"
                 " cp.async.cg.shared.global [%0], [gp], 16; }"
                 :: "r"(s), "l"(g) : "memory");
}
#define CP_COMMIT() asm volatile("cp.async.commit_group;" ::: "memory")
#define CP_WAIT(n)  asm volatile("cp.async.wait_group %0;" :: "n"(n) : "memory")
#define LDSM_X4(R, addr) \
    asm volatile("ldmatrix.sync.aligned.m8n8.x4.shared.b16 {%0,%1,%2,%3}, [%4];" \
        : "=r"((R)[0]), "=r"((R)[1]), "=r"((R)[2]), "=r"((R)[3]) : "r"(addr))
#define LDSM_X4T(R, addr) \
    asm volatile("ldmatrix.sync.aligned.m8n8.x4.trans.shared.b16 {%0,%1,%2,%3}, [%4];" \
        : "=r"((R)[0]), "=r"((R)[1]), "=r"((R)[2]), "=r"((R)[3]) : "r"(addr))

// ---------------------------------------------------------------------------
// Fused fp32 -> fp16 conversion: blocks [0, 8192) convert x,
// blocks [8192, 9216) convert Wo.
// ---------------------------------------------------------------------------
__global__ __launch_bounds__(256) void conv_fused_kernel(
    const float4* __restrict__ x, uint32_t* __restrict__ xh,
    const float4* __restrict__ wo, uint32_t* __restrict__ woh)
{
    const float4* src;
    uint32_t* dst;
    int i;
    if (blockIdx.x < 8192) {
        src = x;  dst = xh;
        i = blockIdx.x * 256 + threadIdx.x;
    } else {
        src = wo; dst = woh;
        i = (blockIdx.x - 8192) * 256 + threadIdx.x;
    }
    float4 v = src[i];
    dst[2 * i]     = pack_h2(v.x, v.y);
    dst[2 * i + 1] = pack_h2(v.z, v.w);
}

// ---------------------------------------------------------------------------
// qkv weight transpose (fp16 hi only)
// ---------------------------------------------------------------------------
__global__ __launch_bounds__(256) void wtrans_kernel(
    const float* __restrict__ Wq, const float* __restrict__ Wk,
    const float* __restrict__ Wv)
{
    __shared__ float tile[64][65];
    const int selh = blockIdx.x;
    const int sel  = selh >> 4;
    const int h    = selh & 15;
    const int d0   = blockIdx.y * 64;
    const float* W  = (sel == 0) ? Wq : (sel == 1) ? Wk : Wv;
    const float* Wb = W + (size_t)h * 1024 * 64;

    const int tid = threadIdx.x;
    for (int idx = tid; idx < 64 * 64; idx += 256) {
        int r = idx >> 6, c = idx & 63;
        tile[r][c] = Wb[(size_t)(d0 + r) * 64 + c];
    }
    __syncthreads();
    const size_t nbase = (size_t)sel * 1024 + h * 64;
    for (int idx = tid; idx < 2048; idx += 256) {
        int r  = idx >> 5;
        int c2 = (idx & 31) * 2;
        size_t o = (nbase + r) * 1024 + d0 + c2;
        *(uint32_t*)&g_wh[o] = pack_h2(tile[c2][r], tile[c2 + 1][r]);
    }
}

// ---------------------------------------------------------------------------
// Pure fp16 GEMM (R15 config): C = Ah @ Bh^T. Warp tile 64x64, block 128x128,
// K-chunk 32, cp.async double-buffered, 2 stages x 20480 B.
// mode 0: write q (scaled)/k/v fp16. mode 1: fp32 out.
// ---------------------------------------------------------------------------
__global__ __launch_bounds__(128, 2) void gemm_kernel(
    const __half* __restrict__ Ah, const __half* __restrict__ Bh,
    float* __restrict__ out, int mode)
{
    extern __shared__ __half dsm[];
    constexpr uint32_t ARR = 10240, STG = 20480;   // 2 stages -> 40960 B

    const int m0 = blockIdx.y * 128;
    const int n0 = blockIdx.x * 128;
    const int tid = threadIdx.x;
    const int w = tid >> 5, lane = tid & 31;
    const int wm = w >> 1, wn = w & 1;
    const int gr = lane >> 2, tg = lane & 3;
    const uint32_t sbase = smem_u32(dsm);

    float C[4][8][4];
    #pragma unroll
    for (int a = 0; a < 4; a++)
        #pragma unroll
        for (int b = 0; b < 8; b++)
            #pragma unroll
            for (int c = 0; c < 4; c++) C[a][b][c] = 0.0f;

    const uint32_t a_rowb = (uint32_t)(wm * 64 + (lane & 7) + ((lane & 8) ? 8 : 0));
    const uint32_t a_coff = (lane & 16) ? 8 : 0;
    const uint32_t b_rowb = (uint32_t)(wn * 64 + (lane & 7) + ((lane & 16) ? 8 : 0));
    const uint32_t b_coff = (lane & 8) ? 8 : 0;

    auto stage_load = [&](int it, int buf) {
        const int k0 = it * 32;
        const uint32_t sa = sbase + (uint32_t)buf * STG;
        #pragma unroll
        for (int i = 0; i < 4; i++) {
            const int idx = tid + 128 * i;
            const int row = idx >> 2;
            const int c4  = idx & 3;
            const uint32_t so = (uint32_t)(row * 80 + c4 * 16);
            cp16(sa + so,       Ah + (size_t)(m0 + row) * 1024 + k0 + c4 * 8);
            cp16(sa + ARR + so, Bh + (size_t)(n0 + row) * 1024 + k0 + c4 * 8);
        }
        CP_COMMIT();
    };

    stage_load(0, 0);
    for (int it = 0; it < 32; it++) {
        const int buf = it & 1;
        CP_WAIT(0);
        __syncthreads();
        if (it + 1 < 32) stage_load(it + 1, 1 - buf);
        const uint32_t sa = sbase + (uint32_t)buf * STG;

        #pragma unroll
        for (int ks = 0; ks < 2; ks++) {
            const uint32_t acol = (uint32_t)(ks * 16) + a_coff;
            const uint32_t bcol = (uint32_t)(ks * 16) + b_coff;
            uint32_t ah[4][4];
            #pragma unroll
            for (int mf = 0; mf < 4; mf++)
                LDSM_X4(ah[mf], sa + (a_rowb + mf * 16) * 80 + acol * 2);
            #pragma unroll
            for (int np = 0; np < 4; np++) {
                uint32_t rh[4];
                LDSM_X4(rh, sa + ARR + (b_rowb + np * 16) * 80 + bcol * 2);
                const int nf0 = np * 2, nf1 = np * 2 + 1;
                #pragma unroll
                for (int mf = 0; mf < 4; mf++) {
                    mma_f16(C[mf][nf0], ah[mf], rh[0], rh[1]);
                    mma_f16(C[mf][nf1], ah[mf], rh[2], rh[3]);
                }
            }
        }
    }

    if (mode == 1) {
        #pragma unroll
        for (int mf = 0; mf < 4; mf++) {
            int row = m0 + wm * 64 + mf * 16 + gr;
            #pragma unroll
            for (int nf = 0; nf < 8; nf++) {
                int col = n0 + wn * 64 + nf * 8 + tg * 2;
                *(float2*)(out + (size_t)row * 1024 + col) =
                    make_float2(C[mf][nf][0], C[mf][nf][1]);
                *(float2*)(out + (size_t)(row + 8) * 1024 + col) =
                    make_float2(C[mf][nf][2], C[mf][nf][3]);
            }
        }
    } else {
        #pragma unroll
        for (int mf = 0; mf < 4; mf++) {
            int row = m0 + wm * 64 + mf * 16 + gr;
            int b = row >> 11, s = row & 2047;
            #pragma unroll
            for (int nf = 0; nf < 8; nf++) {
                int col = n0 + wn * 64 + nf * 8 + tg * 2;
                int sel = col >> 10;
                int hh  = (col >> 6) & 15;
                int kk  = col & 63;
                __half* dst = (sel == 0) ? g_qh : (sel == 1) ? g_kh : g_vh;
                float sc = (sel == 0) ? QSCALE : 1.0f;
                size_t i0 = ((size_t)(b * 16 + hh) * 2048 + s) * 64 + kk;
                size_t i1 = i0 + 8 * 64;
                *(uint32_t*)&dst[i0] = pack_h2(C[mf][nf][0] * sc, C[mf][nf][1] * sc);
                *(uint32_t*)&dst[i1] = pack_h2(C[mf][nf][2] * sc, C[mf][nf][3] * sc);
            }
        }
    }
}

// ---------------------------------------------------------------------------
// Flash attention (causal), pure fp16 (R15 config).
// ---------------------------------------------------------------------------
__global__ __launch_bounds__(256, 2) void attn_kernel()
{
    extern __shared__ __half dsmh[];
    constexpr uint32_t KARR = 9216;           // 64 rows * 144 B
    constexpr uint32_t KSTG = 18432;          // K + V per stage
    constexpr uint32_t QOFF = 36864;

    const int qb = (int)gridDim.x - 1 - (int)blockIdx.x;
    const int q0 = qb * 128;
    const int bh = blockIdx.y;
    const int tid = threadIdx.x;
    const int w = tid >> 5, lane = tid & 31;
    const int gr = lane >> 2, tg = lane & 3;
    const size_t seqbase = (size_t)bh * 2048;
    const uint32_t sbase = smem_u32(dsmh);

    {
        const __half* qh = g_qh + (seqbase + q0) * 64;
        #pragma unroll
        for (int i = 0; i < 4; i++) {
            int c = tid + 256 * i;
            int row = c >> 3, c8 = c & 7;
            uint32_t so = (uint32_t)(row * 144 + c8 * 16);
            cp16(sbase + QOFF + so, qh + (size_t)row * 64 + c8 * 8);
        }
        CP_COMMIT();
    }

    auto stage_kv = [&](int it, int buf) {
        const int kv0 = it * 64;
        const uint32_t sa = sbase + (uint32_t)buf * KSTG;
        const __half* kh = g_kh + (seqbase + kv0) * 64;
        const __half* vh = g_vh + (seqbase + kv0) * 64;
        #pragma unroll
        for (int i = 0; i < 2; i++) {
            int c = tid + 256 * i;
            int row = c >> 3, c8 = c & 7;
            uint32_t so = (uint32_t)(row * 144 + c8 * 16);
            size_t go = (size_t)row * 64 + c8 * 8;
            cp16(sa + so,        kh + go);
            cp16(sa + KARR + so, vh + go);
        }
        CP_COMMIT();
    };

    const int nt = qb * 2 + 2;
    stage_kv(0, 0);
    CP_WAIT(1);
    __syncthreads();

    uint32_t Qh[4][4];
    {
        const uint32_t q_rowb = (uint32_t)(w * 16 + (lane & 7) + ((lane & 8) ? 8 : 0));
        const uint32_t q_coff = (lane & 16) ? 8 : 0;
        #pragma unroll
        for (int ks = 0; ks < 4; ks++)
            LDSM_X4(Qh[ks], sbase + QOFF + q_rowb * 144 + (ks * 16 + q_coff) * 2);
    }

    float O[8][4];
    #pragma unroll
    for (int nf = 0; nf < 8; nf++)
        #pragma unroll
        for (int c = 0; c < 4; c++) O[nf][c] = 0.0f;
    float m0v = -1e30f, m1v = -1e30f, l0v = 0.0f, l1v = 0.0f;
    const int wrow = q0 + w * 16;

    const uint32_t k_rowb = (uint32_t)((lane & 7) + ((lane & 16) ? 8 : 0));
    const uint32_t k_coff = (lane & 8) ? 8 : 0;
    const uint32_t v_coff = (lane & 16) ? 8 : 0;

    for (int it = 0; it < nt; it++) {
        const int buf = it & 1;
        CP_WAIT(0);
        __syncthreads();
        if (it + 1 < nt) stage_kv(it + 1, 1 - buf);
        const int kv0 = it * 64;

        if (kv0 <= wrow + 15) {
            const uint32_t sa = sbase + (uint32_t)buf * KSTG;

            float Sf[8][4];
            #pragma unroll
            for (int nf = 0; nf < 8; nf++)
                #pragma unroll
                for (int c = 0; c < 4; c++) Sf[nf][c] = 0.0f;

            #pragma unroll
            for (int ks = 0; ks < 4; ks++) {
                const uint32_t kcol = (uint32_t)(ks * 16) + k_coff;
                uint32_t rk[4][4];
                #pragma unroll
                for (int np = 0; np < 4; np++)
                    LDSM_X4(rk[np], sa + (k_rowb + np * 16) * 144 + kcol * 2);
                #pragma unroll
                for (int np = 0; np < 4; np++) {
                    mma_f16(Sf[np * 2],     Qh[ks], rk[np][0], rk[np][1]);
                    mma_f16(Sf[np * 2 + 1], Qh[ks], rk[np][2], rk[np][3]);
                }
            }

            if (kv0 + 63 > wrow) {
                const int r0g = wrow + gr;
                #pragma unroll
                for (int nf = 0; nf < 8; nf++) {
                    int col = kv0 + nf * 8 + tg * 2;
                    if (col     > r0g)     Sf[nf][0] = -1e30f;
                    if (col + 1 > r0g)     Sf[nf][1] = -1e30f;
                    if (col     > r0g + 8) Sf[nf][2] = -1e30f;
                    if (col + 1 > r0g + 8) Sf[nf][3] = -1e30f;
                }
            }

            float mx0 = -1e30f, mx1 = -1e30f;
            #pragma unroll
            for (int nf = 0; nf < 8; nf++) {
                mx0 = fmaxf(mx0, fmaxf(Sf[nf][0], Sf[nf][1]));
                mx1 = fmaxf(mx1, fmaxf(Sf[nf][2], Sf[nf][3]));
            }
            mx0 = fmaxf(mx0, __shfl_xor_sync(0xffffffffu, mx0, 1));
            mx0 = fmaxf(mx0, __shfl_xor_sync(0xffffffffu, mx0, 2));
            mx1 = fmaxf(mx1, __shfl_xor_sync(0xffffffffu, mx1, 1));
            mx1 = fmaxf(mx1, __shfl_xor_sync(0xffffffffu, mx1, 2));

            float mn0 = fmaxf(m0v, mx0), mn1 = fmaxf(m1v, mx1);
            float a0 = fast_exp2(m0v - mn0), a1 = fast_exp2(m1v - mn1);
            float s0 = 0.0f, s1 = 0.0f;
            #pragma unroll
            for (int nf = 0; nf < 8; nf++) {
                Sf[nf][0] = fast_exp2(Sf[nf][0] - mn0); s0 += Sf[nf][0];
                Sf[nf][1] = fast_exp2(Sf[nf][1] - mn0); s0 += Sf[nf][1];
                Sf[nf][2] = fast_exp2(Sf[nf][2] - mn1); s1 += Sf[nf][2];
                Sf[nf][3] = fast_exp2(Sf[nf][3] - mn1); s1 += Sf[nf][3];
            }
            s0 += __shfl_xor_sync(0xffffffffu, s0, 1);
            s0 += __shfl_xor_sync(0xffffffffu, s0, 2);
            s1 += __shfl_xor_sync(0xffffffffu, s1, 1);
            s1 += __shfl_xor_sync(0xffffffffu, s1, 2);

            l0v = l0v * a0 + s0;  l1v = l1v * a1 + s1;
            m0v = mn0;            m1v = mn1;
            #pragma unroll
            for (int nf = 0; nf < 8; nf++) {
                O[nf][0] *= a0; O[nf][1] *= a0;
                O[nf][2] *= a1; O[nf][3] *= a1;
            }

            #pragma unroll
            for (int ks = 0; ks < 4; ks++) {
                uint32_t Ph[4];
                Ph[0] = pack_h2(Sf[2 * ks][0],     Sf[2 * ks][1]);
                Ph[1] = pack_h2(Sf[2 * ks][2],     Sf[2 * ks][3]);
                Ph[2] = pack_h2(Sf[2 * ks + 1][0], Sf[2 * ks + 1][1]);
                Ph[3] = pack_h2(Sf[2 * ks + 1][2], Sf[2 * ks + 1][3]);
                const uint32_t v_rowb = (uint32_t)(ks * 16 + (lane & 15));
                uint32_t rv[4][4];
                #pragma unroll
                for (int np = 0; np < 4; np++)
                    LDSM_X4T(rv[np], sa + KARR + v_rowb * 144
                                   + ((uint32_t)(np * 16) + v_coff) * 2);
                #pragma unroll
                for (int np = 0; np < 4; np++) {
                    mma_f16(O[np * 2],     Ph, rv[np][0], rv[np][1]);
                    mma_f16(O[np * 2 + 1], Ph, rv[np][2], rv[np][3]);
                }
            }
        }
    }

    const float inv0 = 1.0f / l0v, inv1 = 1.0f / l1v;
    const int b = bh >> 4, h = bh & 15;
    const int row0 = q0 + w * 16 + gr;
    const size_t base0 = ((size_t)(b * 2048) + row0) * 1024 + h * 64;
    const size_t base1 = base0 + (size_t)8 * 1024;
    #pragma unroll
    for (int nf = 0; nf < 8; nf++) {
        int c = nf * 8 + tg * 2;
        *(uint32_t*)&g_atth[base0 + c] = pack_h2(O[nf][0] * inv0, O[nf][1] * inv0);
        *(uint32_t*)&g_atth[base1 + c] = pack_h2(O[nf][2] * inv1, O[nf][3] * inv1);
    }
}

// ---------------------------------------------------------------------------
extern "C" void kernel_launch(void* const* d_in, const int* in_sizes, int n_in,
                              void* d_out, int out_size)
{
    const float* x  = (const float*)d_in[0];
    const float* Wq = (const float*)d_in[1];
    const float* Wk = (const float*)d_in[2];
    const float* Wv = (const float*)d_in[3];
    const float* Wo = (const float*)d_in[4];
    float* out = (float*)d_out;

    void *p_xh, *p_wh, *p_woh, *p_atth;
    cudaGetSymbolAddress(&p_xh,  g_xh);
    cudaGetSymbolAddress(&p_wh,  g_wh);
    cudaGetSymbolAddress(&p_woh, g_woh);
    cudaGetSymbolAddress(&p_atth, g_atth);

    const int gemm_shm = 40960;   // 2 stages x 20480 (K-chunk 32)
    const int attn_shm = 55296;   // KV 2x18432 + Q 18432
    cudaFuncSetAttribute(gemm_kernel, cudaFuncAttributeMaxDynamicSharedMemorySize, gemm_shm);
    cudaFuncSetAttribute(attn_kernel, cudaFuncAttributeMaxDynamicSharedMemorySize, attn_shm);

    conv_fused_kernel<<<9216, 256>>>((const float4*)x, (uint32_t*)p_xh,
                                     (const float4*)Wo, (uint32_t*)p_woh);

    wtrans_kernel<<<dim3(48, 16), 256>>>(Wq, Wk, Wv);

    gemm_kernel<<<dim3(24, 64), 128, gemm_shm>>>(
        (const __half*)p_xh, (const __half*)p_wh, nullptr, 0);

    attn_kernel<<<dim3(S_ / 128, 64), 256, attn_shm>>>();

    gemm_kernel<<<dim3(8, 64), 128, gemm_shm>>>(
        (const __half*)p_atth, (const __half*)p_woh, out, 1);
}